// round 13
// baseline (speedup 1.0000x reference)
#include <cuda_runtime.h>
#include <cuda_fp16.h>
#include <cstddef>

// LightGCN, CSR-gather, fp16 propagated storage, premultiplied edge weights,
// unordered segment allocation, need-flag-restricted layer-2 gather.
//   K0 convdeg  : t16 = fp16(tables); degree histogram; batch flags
//   K1 segalloc : rs[i]; block-scan of 8-padded degrees + one atomicAdd per
//                 block -> seg[i] = (beg, nblk8); zero own pad slots
//   K2 fill     : packed adjacency (src_id, w = rs[dst]*rs[src]); cursor =
//                 atomic countdown on g_deg; propagate need2 to batch nbrs
//   K3 gather1  : x1h = gather(t16)                (all nodes)
//   K4 gather2  : x2h = gather(x1h)                (need2 nodes only)
//   K5 score    : fused batch final layer (x3 gather) + dots + L2 reg

#define NU_MAX 100000
#define NI_MAX 50000
#define N_MAX  (NU_MAX + NI_MAX)
#define E_MAX  1600000
#define EMB_D  64
#define SEG_B  256
#define ADJ_ENTRIES ((size_t)2 * E_MAX + (size_t)7 * N_MAX + 64)

__device__ int           g_deg[N_MAX];
__device__ float         g_rs[N_MAX];
__device__ int2          g_seg[N_MAX];         // (beg, nblk8) per node
__device__ int           g_ctr[1];             // segment allocation cursor
__device__ unsigned char g_fbatch[N_MAX];      // node is in the batch
__device__ unsigned char g_need2[N_MAX];       // x2h[node] will be read
__device__ int2          g_adj[ADJ_ENTRIES];   // (src_id, w_bits)
__device__ __half2       g_t16[(size_t)N_MAX * (EMB_D / 2)];
__device__ __half2       g_x1h[(size_t)N_MAX * (EMB_D / 2)];
__device__ __half2       g_x2h[(size_t)N_MAX * (EMB_D / 2)];

// ---------------------------------------------------------------------------
// K0: fp16 table copy + degree histogram + batch flag init (independent work)
__global__ void convdeg_kernel(const float2* __restrict__ ut, const float2* __restrict__ it,
                               const int* __restrict__ eu, const int* __restrict__ ei,
                               const int* __restrict__ users, const int* __restrict__ pos,
                               const int* __restrict__ neg,
                               int E, int nu, int nu2, int ntot2, int B) {
    int i = blockIdx.x * blockDim.x + threadIdx.x;
    if (i < ntot2) {
        float2 v = (i < nu2) ? ut[i] : it[i - nu2];
        g_t16[i] = __floats2half2_rn(v.x, v.y);
    }
    if (i < E) {
        atomicAdd(&g_deg[eu[i]], 1);
        atomicAdd(&g_deg[nu + ei[i]], 1);
    }
    if (i < 3 * B) {
        int node;
        if (i < B)          node = users[i];
        else if (i < 2 * B) node = nu + pos[i - B];
        else                node = nu + neg[i - 2 * B];
        g_fbatch[node] = 1;
        g_need2[node]  = 1;                    // score reads x2h[node] directly
    }
}

// K1: rs + unordered segment allocation + pad-slot zeroing (no adj memset).
__global__ void segalloc_kernel(int N) {
    __shared__ int sh[SEG_B];
    __shared__ int base;
    int tid = threadIdx.x;
    int i = blockIdx.x * SEG_B + tid;
    int d = (i < N) ? g_deg[i] : 0;
    if (i < N) g_rs[i] = rsqrtf(fmaxf((float)d, 1.0f));
    int pd = (d + 7) & ~7;                     // pad degree to multiple of 8
    sh[tid] = pd;
    __syncthreads();
    #pragma unroll
    for (int o = 1; o < SEG_B; o <<= 1) {
        int t = (tid >= o) ? sh[tid - o] : 0;
        __syncthreads();
        sh[tid] += t;
        __syncthreads();
    }
    if (tid == SEG_B - 1) base = atomicAdd(&g_ctr[0], sh[tid]);
    __syncthreads();
    if (i < N) {
        int beg = base + sh[tid] - pd;
        g_seg[i] = make_int2(beg, pd >> 3);
        for (int j = d; j < pd; ++j)           // zero own pad slots (<=7)
            g_adj[(size_t)beg + j] = make_int2(0, 0);
    }
}

// K2: fill packed adjacency (src, w_premult); cursor = countdown on g_deg.
// Also propagates need2: neighbors of batch nodes will have x2h read.
__global__ void fill_kernel(const int* __restrict__ eu, const int* __restrict__ ei,
                            int E, int nu) {
    int e = blockIdx.x * blockDim.x + threadIdx.x;
    if (e >= E) return;
    int u = eu[e];
    int r2 = nu + ei[e];
    float w = g_rs[u] * g_rs[r2];
    int wb = __float_as_int(w);
    int p1 = atomicAdd(&g_deg[u], -1) - 1;
    g_adj[(size_t)__ldg(&g_seg[u].x) + p1] = make_int2(r2, wb);
    int p2 = atomicAdd(&g_deg[r2], -1) - 1;
    g_adj[(size_t)__ldg(&g_seg[r2].x) + p2] = make_int2(u, wb);
    if (g_fbatch[u])  g_need2[r2] = 1;
    if (g_fbatch[r2]) g_need2[u]  = 1;
}

// gather: 8 neighbors per iteration, all 8 row loads independent.
__device__ __forceinline__ float2 gather_row_p(const __half2* __restrict__ src,
                                               int node, int lane) {
    int2 seg = __ldg(&g_seg[node]);
    const int4* a4 = reinterpret_cast<const int4*>(g_adj + seg.x);
    int nblk = seg.y;
    float sx = 0.0f, sy = 0.0f;
    for (int j = 0; j < nblk; ++j) {
        int4 p0 = __ldg(&a4[4 * j]);
        int4 p1 = __ldg(&a4[4 * j + 1]);
        int4 p2 = __ldg(&a4[4 * j + 2]);
        int4 p3 = __ldg(&a4[4 * j + 3]);
        float2 v0 = __half22float2(__ldg(src + ((size_t)p0.x << 5) + lane));
        float2 v1 = __half22float2(__ldg(src + ((size_t)p0.z << 5) + lane));
        float2 v2 = __half22float2(__ldg(src + ((size_t)p1.x << 5) + lane));
        float2 v3 = __half22float2(__ldg(src + ((size_t)p1.z << 5) + lane));
        float2 v4 = __half22float2(__ldg(src + ((size_t)p2.x << 5) + lane));
        float2 v5 = __half22float2(__ldg(src + ((size_t)p2.z << 5) + lane));
        float2 v6 = __half22float2(__ldg(src + ((size_t)p3.x << 5) + lane));
        float2 v7 = __half22float2(__ldg(src + ((size_t)p3.z << 5) + lane));
        float w0 = __int_as_float(p0.y), w1 = __int_as_float(p0.w);
        float w2 = __int_as_float(p1.y), w3 = __int_as_float(p1.w);
        float w4 = __int_as_float(p2.y), w5 = __int_as_float(p2.w);
        float w6 = __int_as_float(p3.y), w7 = __int_as_float(p3.w);
        sx += w0 * v0.x + w1 * v1.x + w2 * v2.x + w3 * v3.x
            + w4 * v4.x + w5 * v5.x + w6 * v6.x + w7 * v7.x;
        sy += w0 * v0.y + w1 * v1.y + w2 * v2.y + w3 * v3.y
            + w4 * v4.y + w5 * v5.y + w6 * v6.y + w7 * v7.y;
    }
    return make_float2(sx, sy);
}

// K3: full propagation layer (all nodes)
__global__ void gatherH_kernel(const __half2* __restrict__ src,
                               __half2* __restrict__ dst, int N) {
    int warp = (blockIdx.x * blockDim.x + threadIdx.x) >> 5;
    int lane = threadIdx.x & 31;
    if (warp >= N) return;
    float2 s = gather_row_p(src, warp, lane);
    dst[(size_t)warp * (EMB_D / 2) + lane] = __floats2half2_rn(s.x, s.y);
}

// K4: propagation layer restricted to need2 nodes
__global__ void gatherH_need_kernel(const __half2* __restrict__ src,
                                    __half2* __restrict__ dst, int N) {
    int warp = (blockIdx.x * blockDim.x + threadIdx.x) >> 5;
    int lane = threadIdx.x & 31;
    if (warp >= N) return;
    if (!g_need2[warp]) return;                // x2h[warp] never read
    float2 s = gather_row_p(src, warp, lane);
    dst[(size_t)warp * (EMB_D / 2) + lane] = __floats2half2_rn(s.x, s.y);
}

// K5: fused final layer + scoring: one warp per batch element.
__global__ void score_kernel(const float* __restrict__ ut, const float* __restrict__ it,
                             const int* __restrict__ users, const int* __restrict__ pos,
                             const int* __restrict__ neg,
                             const __half2* __restrict__ x1h,
                             const __half2* __restrict__ x2h,
                             float* __restrict__ out, int B, int nu) {
    int warp = (blockIdx.x * blockDim.x + threadIdx.x) >> 5;
    int lane = threadIdx.x & 31;
    if (warp >= B) return;

    int nodes[3];
    nodes[0] = users[warp];
    nodes[1] = nu + pos[warp];
    nodes[2] = nu + neg[warp];

    float2 f[3];
    float rg = 0.0f;
    #pragma unroll
    for (int k = 0; k < 3; ++k) {
        int node = nodes[k];
        float2 x3 = gather_row_p(x2h, node, lane);
        const float* base0 = (node < nu) ? (ut + (size_t)node * EMB_D)
                                         : (it + (size_t)(node - nu) * EMB_D);
        float2 x0 = reinterpret_cast<const float2*>(base0)[lane];
        float2 x1 = __half22float2(x1h[(size_t)node * (EMB_D / 2) + lane]);
        float2 x2 = __half22float2(x2h[(size_t)node * (EMB_D / 2) + lane]);
        f[k] = make_float2(0.25f * (x0.x + x1.x + x2.x + x3.x),
                           0.25f * (x0.y + x1.y + x2.y + x3.y));
        rg += x0.x * x0.x + x0.y * x0.y;
    }

    float ps = f[0].x * f[1].x + f[0].y * f[1].y;
    float ns = f[0].x * f[2].x + f[0].y * f[2].y;

    #pragma unroll
    for (int o = 16; o > 0; o >>= 1) {
        ps += __shfl_down_sync(0xFFFFFFFFu, ps, o);
        ns += __shfl_down_sync(0xFFFFFFFFu, ns, o);
        rg += __shfl_down_sync(0xFFFFFFFFu, rg, o);
    }
    if (lane == 0) {
        out[warp]     = ps;
        out[B + warp] = ns;
        atomicAdd(&out[2 * B], rg * (1e-4f / (float)B));
    }
}

// ---------------------------------------------------------------------------
extern "C" void kernel_launch(void* const* d_in, const int* in_sizes, int n_in,
                              void* d_out, int out_size) {
    const float* ut    = (const float*)d_in[0];
    const float* it    = (const float*)d_in[1];
    const int*   eu    = (const int*)d_in[2];
    const int*   ei    = (const int*)d_in[3];
    const int*   users = (const int*)d_in[4];
    const int*   pos   = (const int*)d_in[5];
    const int*   neg   = (const int*)d_in[6];
    float*       out   = (float*)d_out;

    const int n_users = in_sizes[0] / EMB_D;
    const int n_items = in_sizes[1] / EMB_D;
    const int E       = in_sizes[2];
    const int B       = in_sizes[4];
    const int N       = n_users + n_items;

    void *p_deg, *p_ctr, *p_fb, *p_n2, *p_t16, *p_x1h, *p_x2h;
    cudaGetSymbolAddress(&p_deg, g_deg);
    cudaGetSymbolAddress(&p_ctr, g_ctr);
    cudaGetSymbolAddress(&p_fb, g_fbatch);
    cudaGetSymbolAddress(&p_n2, g_need2);
    cudaGetSymbolAddress(&p_t16, g_t16);
    cudaGetSymbolAddress(&p_x1h, g_x1h);
    cudaGetSymbolAddress(&p_x2h, g_x2h);

    const int T = 256;

    // memsets (small arrays only; the 34MB adjacency memset is gone)
    cudaMemsetAsync(p_deg, 0, (size_t)N * sizeof(int), 0);
    cudaMemsetAsync(p_ctr, 0, sizeof(int), 0);
    cudaMemsetAsync(p_fb, 0, (size_t)N, 0);
    cudaMemsetAsync(p_n2, 0, (size_t)N, 0);
    cudaMemsetAsync(out + 2 * B, 0, sizeof(float), 0);

    // K0: fused fp16 convert + degree histogram + batch flags
    const int ntot2 = N * (EMB_D / 2);
    int k0n = (ntot2 > E) ? ntot2 : E;
    convdeg_kernel<<<(k0n + T - 1) / T, T>>>((const float2*)ut, (const float2*)it,
                                             eu, ei, users, pos, neg,
                                             E, n_users,
                                             n_users * (EMB_D / 2), ntot2, B);

    // K1: rs + segment allocation + pad zeroing
    segalloc_kernel<<<(N + SEG_B - 1) / SEG_B, SEG_B>>>(N);

    // K2: adjacency fill + need2 propagation
    fill_kernel<<<(E + T - 1) / T, T>>>(eu, ei, E, n_users);

    // K3/K4: propagation layers
    const int wpb = T / 32;
    const int gblocks = (N + wpb - 1) / wpb;
    gatherH_kernel<<<gblocks, T>>>((const __half2*)p_t16, (__half2*)p_x1h, N);
    gatherH_need_kernel<<<gblocks, T>>>((const __half2*)p_x1h, (__half2*)p_x2h, N);

    // K5: fused final layer + scoring
    score_kernel<<<(B + wpb - 1) / wpb, T>>>(ut, it, users, pos, neg,
                                             (const __half2*)p_x1h,
                                             (const __half2*)p_x2h,
                                             out, B, n_users);
}

// round 14
// speedup vs baseline: 1.0656x; 1.0656x over previous
#include <cuda_runtime.h>
#include <cuda_fp16.h>
#include <cstddef>

// LightGCN, CSR-gather, fp16 propagated storage, premultiplied edge weights,
// unordered segment allocation, pad-zeroing fused into segalloc.
//   K0 convdeg  : t16 = fp16(tables) AND stacked degree histogram
//   K1 segalloc : rs[i]; block-scan of 8-padded degrees + one atomicAdd per
//                 block -> seg[i] = (beg, nblk8); zero own pad slots
//   K2 fill     : packed adjacency (src_id, w = rs[dst]*rs[src]); cursor =
//                 atomic countdown on g_deg (dead after segalloc)
//   K3 gather1  : x1h = gather(t16)
//   K4 gather2  : x2h = gather(x1h)
//   K5 score    : fused batch final layer (x3 gather) + dots + L2 reg

#define NU_MAX 100000
#define NI_MAX 50000
#define N_MAX  (NU_MAX + NI_MAX)
#define E_MAX  1600000
#define EMB_D  64
#define SEG_B  256
#define ADJ_ENTRIES ((size_t)2 * E_MAX + (size_t)7 * N_MAX + 64)

__device__ int     g_deg[N_MAX];
__device__ float   g_rs[N_MAX];
__device__ int2    g_seg[N_MAX];               // (beg, nblk8) per node
__device__ int     g_ctr[1];                   // segment allocation cursor
__device__ int2    g_adj[ADJ_ENTRIES];         // (src_id, w_bits)
__device__ __half2 g_t16[(size_t)N_MAX * (EMB_D / 2)];
__device__ __half2 g_x1h[(size_t)N_MAX * (EMB_D / 2)];
__device__ __half2 g_x2h[(size_t)N_MAX * (EMB_D / 2)];

// ---------------------------------------------------------------------------
// K0: fp16 table copy + stacked degree histogram (independent work, one grid)
__global__ void convdeg_kernel(const float2* __restrict__ ut, const float2* __restrict__ it,
                               const int* __restrict__ eu, const int* __restrict__ ei,
                               int E, int nu, int nu2, int ntot2) {
    int i = blockIdx.x * blockDim.x + threadIdx.x;
    if (i < ntot2) {
        float2 v = (i < nu2) ? ut[i] : it[i - nu2];
        g_t16[i] = __floats2half2_rn(v.x, v.y);
    }
    if (i < E) {
        atomicAdd(&g_deg[eu[i]], 1);
        atomicAdd(&g_deg[nu + ei[i]], 1);
    }
}

// K1: rs + unordered segment allocation + pad-slot zeroing (no adj memset).
__global__ void segalloc_kernel(int N) {
    __shared__ int sh[SEG_B];
    __shared__ int base;
    int tid = threadIdx.x;
    int i = blockIdx.x * SEG_B + tid;
    int d = (i < N) ? g_deg[i] : 0;
    if (i < N) g_rs[i] = rsqrtf(fmaxf((float)d, 1.0f));
    int pd = (d + 7) & ~7;                     // pad degree to multiple of 8
    sh[tid] = pd;
    __syncthreads();
    #pragma unroll
    for (int o = 1; o < SEG_B; o <<= 1) {
        int t = (tid >= o) ? sh[tid - o] : 0;
        __syncthreads();
        sh[tid] += t;
        __syncthreads();
    }
    if (tid == SEG_B - 1) base = atomicAdd(&g_ctr[0], sh[tid]);
    __syncthreads();
    if (i < N) {
        int beg = base + sh[tid] - pd;
        g_seg[i] = make_int2(beg, pd >> 3);
        for (int j = d; j < pd; ++j)           // zero own pad slots (<=7)
            g_adj[(size_t)beg + j] = make_int2(0, 0);
    }
}

// K2: fill packed adjacency (src, w_premult). Cursor = countdown on g_deg.
// Pad slots already zeroed by segalloc => contribute exactly zero.
__global__ void fill_kernel(const int* __restrict__ eu, const int* __restrict__ ei,
                            int E, int nu) {
    int e = blockIdx.x * blockDim.x + threadIdx.x;
    if (e >= E) return;
    int u = eu[e];
    int r2 = nu + ei[e];
    float w = g_rs[u] * g_rs[r2];
    int wb = __float_as_int(w);
    int p1 = atomicAdd(&g_deg[u], -1) - 1;
    g_adj[(size_t)__ldg(&g_seg[u].x) + p1] = make_int2(r2, wb);
    int p2 = atomicAdd(&g_deg[r2], -1) - 1;
    g_adj[(size_t)__ldg(&g_seg[r2].x) + p2] = make_int2(u, wb);
}

// gather: 8 neighbors per iteration, all 8 row loads independent.
__device__ __forceinline__ float2 gather_row_p(const __half2* __restrict__ src,
                                               int node, int lane) {
    int2 seg = __ldg(&g_seg[node]);
    const int4* a4 = reinterpret_cast<const int4*>(g_adj + seg.x);
    int nblk = seg.y;
    float sx = 0.0f, sy = 0.0f;
    for (int j = 0; j < nblk; ++j) {
        int4 p0 = __ldg(&a4[4 * j]);
        int4 p1 = __ldg(&a4[4 * j + 1]);
        int4 p2 = __ldg(&a4[4 * j + 2]);
        int4 p3 = __ldg(&a4[4 * j + 3]);
        float2 v0 = __half22float2(__ldg(src + ((size_t)p0.x << 5) + lane));
        float2 v1 = __half22float2(__ldg(src + ((size_t)p0.z << 5) + lane));
        float2 v2 = __half22float2(__ldg(src + ((size_t)p1.x << 5) + lane));
        float2 v3 = __half22float2(__ldg(src + ((size_t)p1.z << 5) + lane));
        float2 v4 = __half22float2(__ldg(src + ((size_t)p2.x << 5) + lane));
        float2 v5 = __half22float2(__ldg(src + ((size_t)p2.z << 5) + lane));
        float2 v6 = __half22float2(__ldg(src + ((size_t)p3.x << 5) + lane));
        float2 v7 = __half22float2(__ldg(src + ((size_t)p3.z << 5) + lane));
        float w0 = __int_as_float(p0.y), w1 = __int_as_float(p0.w);
        float w2 = __int_as_float(p1.y), w3 = __int_as_float(p1.w);
        float w4 = __int_as_float(p2.y), w5 = __int_as_float(p2.w);
        float w6 = __int_as_float(p3.y), w7 = __int_as_float(p3.w);
        sx += w0 * v0.x + w1 * v1.x + w2 * v2.x + w3 * v3.x
            + w4 * v4.x + w5 * v5.x + w6 * v6.x + w7 * v7.x;
        sy += w0 * v0.y + w1 * v1.y + w2 * v2.y + w3 * v3.y
            + w4 * v4.y + w5 * v5.y + w6 * v6.y + w7 * v7.y;
    }
    return make_float2(sx, sy);
}

// K3/K4: full-graph propagation layer: dst = gather(src), fp16 out
__global__ void gatherH_kernel(const __half2* __restrict__ src,
                               __half2* __restrict__ dst, int N) {
    int warp = (blockIdx.x * blockDim.x + threadIdx.x) >> 5;
    int lane = threadIdx.x & 31;
    if (warp >= N) return;
    float2 s = gather_row_p(src, warp, lane);
    dst[(size_t)warp * (EMB_D / 2) + lane] = __floats2half2_rn(s.x, s.y);
}

// K5: fused final layer + scoring: one warp per batch element.
__global__ void score_kernel(const float* __restrict__ ut, const float* __restrict__ it,
                             const int* __restrict__ users, const int* __restrict__ pos,
                             const int* __restrict__ neg,
                             const __half2* __restrict__ x1h,
                             const __half2* __restrict__ x2h,
                             float* __restrict__ out, int B, int nu) {
    int warp = (blockIdx.x * blockDim.x + threadIdx.x) >> 5;
    int lane = threadIdx.x & 31;
    if (warp >= B) return;

    int nodes[3];
    nodes[0] = users[warp];
    nodes[1] = nu + pos[warp];
    nodes[2] = nu + neg[warp];

    float2 f[3];
    float rg = 0.0f;
    #pragma unroll
    for (int k = 0; k < 3; ++k) {
        int node = nodes[k];
        float2 x3 = gather_row_p(x2h, node, lane);
        const float* base0 = (node < nu) ? (ut + (size_t)node * EMB_D)
                                         : (it + (size_t)(node - nu) * EMB_D);
        float2 x0 = reinterpret_cast<const float2*>(base0)[lane];
        float2 x1 = __half22float2(x1h[(size_t)node * (EMB_D / 2) + lane]);
        float2 x2 = __half22float2(x2h[(size_t)node * (EMB_D / 2) + lane]);
        f[k] = make_float2(0.25f * (x0.x + x1.x + x2.x + x3.x),
                           0.25f * (x0.y + x1.y + x2.y + x3.y));
        rg += x0.x * x0.x + x0.y * x0.y;
    }

    float ps = f[0].x * f[1].x + f[0].y * f[1].y;
    float ns = f[0].x * f[2].x + f[0].y * f[2].y;

    #pragma unroll
    for (int o = 16; o > 0; o >>= 1) {
        ps += __shfl_down_sync(0xFFFFFFFFu, ps, o);
        ns += __shfl_down_sync(0xFFFFFFFFu, ns, o);
        rg += __shfl_down_sync(0xFFFFFFFFu, rg, o);
    }
    if (lane == 0) {
        out[warp]     = ps;
        out[B + warp] = ns;
        atomicAdd(&out[2 * B], rg * (1e-4f / (float)B));
    }
}

// ---------------------------------------------------------------------------
extern "C" void kernel_launch(void* const* d_in, const int* in_sizes, int n_in,
                              void* d_out, int out_size) {
    const float* ut    = (const float*)d_in[0];
    const float* it    = (const float*)d_in[1];
    const int*   eu    = (const int*)d_in[2];
    const int*   ei    = (const int*)d_in[3];
    const int*   users = (const int*)d_in[4];
    const int*   pos   = (const int*)d_in[5];
    const int*   neg   = (const int*)d_in[6];
    float*       out   = (float*)d_out;

    const int n_users = in_sizes[0] / EMB_D;
    const int n_items = in_sizes[1] / EMB_D;
    const int E       = in_sizes[2];
    const int B       = in_sizes[4];
    const int N       = n_users + n_items;

    void *p_deg, *p_ctr, *p_t16, *p_x1h, *p_x2h;
    cudaGetSymbolAddress(&p_deg, g_deg);
    cudaGetSymbolAddress(&p_ctr, g_ctr);
    cudaGetSymbolAddress(&p_t16, g_t16);
    cudaGetSymbolAddress(&p_x1h, g_x1h);
    cudaGetSymbolAddress(&p_x2h, g_x2h);

    const int T = 256;

    // memsets (small arrays only; no 34MB adjacency memset)
    cudaMemsetAsync(p_deg, 0, (size_t)N * sizeof(int), 0);
    cudaMemsetAsync(p_ctr, 0, sizeof(int), 0);
    cudaMemsetAsync(out + 2 * B, 0, sizeof(float), 0);

    // K0: fused fp16 convert + degree histogram
    const int ntot2 = N * (EMB_D / 2);
    const int k0n = (ntot2 > E) ? ntot2 : E;
    convdeg_kernel<<<(k0n + T - 1) / T, T>>>((const float2*)ut, (const float2*)it,
                                             eu, ei, E, n_users,
                                             n_users * (EMB_D / 2), ntot2);

    // K1: rs + segment allocation + pad zeroing
    segalloc_kernel<<<(N + SEG_B - 1) / SEG_B, SEG_B>>>(N);

    // K2: adjacency fill
    fill_kernel<<<(E + T - 1) / T, T>>>(eu, ei, E, n_users);

    // K3/K4: two full propagation layers
    const int wpb = T / 32;
    const int gblocks = (N + wpb - 1) / wpb;
    gatherH_kernel<<<gblocks, T>>>((const __half2*)p_t16, (__half2*)p_x1h, N);
    gatherH_kernel<<<gblocks, T>>>((const __half2*)p_x1h, (__half2*)p_x2h, N);

    // K5: fused final layer + scoring
    score_kernel<<<(B + wpb - 1) / wpb, T>>>(ut, it, users, pos, neg,
                                             (const __half2*)p_x1h,
                                             (const __half2*)p_x2h,
                                             out, B, n_users);
}